// round 1
// baseline (speedup 1.0000x reference)
#include <cuda_runtime.h>

typedef unsigned long long ULL;

// ---------- packed fp32x2 helpers (FFMA2 path; ptxas never auto-fuses) ----------
__device__ __forceinline__ void ffma2(ULL &d, ULL a, ULL b) {
    asm("fma.rn.f32x2 %0, %1, %2, %0;" : "+l"(d) : "l"(a), "l"(b));
}
__device__ __forceinline__ float2 unpack2(ULL v) {
    float2 f; asm("mov.b64 {%0,%1}, %2;" : "=f"(f.x), "=f"(f.y) : "l"(v)); return f;
}
__device__ __forceinline__ ULL pack2(float lo, float hi) {
    ULL r; asm("mov.b64 %0, {%1,%2};" : "=l"(r) : "f"(lo), "f"(hi)); return r;
}

// ---------- activations (MUFU-based, overflow-safe) ----------
__device__ __forceinline__ float sigf(float x)  { return __fdividef(1.f, 1.f + __expf(-x)); }
__device__ __forceinline__ float tanhf2(float x){ return 2.f * sigf(2.f * x) - 1.f; }

// ---------- problem constants ----------
constexpr int B = 512, T = 512, H = 64;
constexpr int RC = 8;            // batch rows per CTA in LSTM kernels
constexpr int NCHUNK = B / RC;   // 64

// ---------- scratch (__device__ globals; allocation is forbidden) ----------
__device__ float g_h0[(long)B * T * 128];     // layer-0 output  [b][t][dir*64+u]   134 MB
__device__ float g_xp1[(long)B * T * 512];    // layer-1 preacts [b*T+t][dir*256+g*64+u]  536 MB
__device__ float g_Bt[128 * 512];             // Wih_l1 transposed [k][n]
__device__ float g_pooled[B * 128];           // per-(b, dir*64+u) sum over t

// =======================================================================
// Layer-0 bidirectional LSTM. grid = (64, 2[dir]), block = 512.
// Thread roles:
//   dot phase:     (rr = tid>>8, g = (tid>>6)&3, u = tid&63) -> gate row g*64+u,
//                  rows rr*4 .. rr*4+3.  W_hh row lives in 64 registers.
//   combine phase: (r = tid>>6, u = tid&63) -> cell state c register-resident.
// =======================================================================
__global__ __launch_bounds__(512, 1) void lstm_l0(
    const float* __restrict__ x,
    const float* __restrict__ Wih_f, const float* __restrict__ Whh_f, const float* __restrict__ b_f,
    const float* __restrict__ Wih_b, const float* __restrict__ Whh_b, const float* __restrict__ b_b)
{
    const int dir = blockIdx.y;
    const int b0  = blockIdx.x * RC;
    const int tid = threadIdx.x;
    const int rr  = tid >> 8;
    const int g   = (tid >> 6) & 3;
    const int u   = tid & 63;
    const int row = g * 64 + u;

    const float* Wih = dir ? Wih_b : Wih_f;
    const float* Whh = dir ? Whh_b : Whh_f;
    const float* bb  = dir ? b_b   : b_f;

    __shared__ float h_s[RC * 64];
    __shared__ float pre_s[RC * 256];

    // W_hh row -> 32 packed f32x2 registers (loop-invariant across all 512 steps)
    ULL w2[32];
    {
        const ULL* wp = (const ULL*)(Whh + row * 64);
        #pragma unroll
        for (int i = 0; i < 32; i++) w2[i] = wp[i];
    }
    const float wih0 = Wih[row * 4 + 0], wih1 = Wih[row * 4 + 1];
    const float wih2 = Wih[row * 4 + 2], wih3 = Wih[row * 4 + 3];
    const float bias = bb[row];

    for (int i = tid; i < RC * 64; i += 512) h_s[i] = 0.f;

    float c = 0.f;
    const int r_cmb = tid >> 6;
    const int u_cmb = tid & 63;

    for (int s = 0; s < T; s++) {
        const int t = dir ? (T - 1 - s) : s;
        __syncthreads();   // h_s from previous combine is visible
        #pragma unroll
        for (int j = 0; j < 4; j++) {
            const int r = rr * 4 + j;
            const float4 xv = *(const float4*)(x + ((long)(b0 + r) * T + t) * 4);
            ULL a0 = 0, a1 = 0;
            const ulonglong2* h4 = (const ulonglong2*)(h_s + r * 64);
            #pragma unroll
            for (int k4 = 0; k4 < 16; k4++) {
                ulonglong2 hv = h4[k4];
                ffma2(a0, w2[2 * k4],     hv.x);
                ffma2(a1, w2[2 * k4 + 1], hv.y);
            }
            const float2 f0 = unpack2(a0), f1 = unpack2(a1);
            pre_s[r * 256 + row] = f0.x + f0.y + f1.x + f1.y + bias
                                 + wih0 * xv.x + wih1 * xv.y + wih2 * xv.z + wih3 * xv.w;
        }
        __syncthreads();
        {
            const float pi = sigf  (pre_s[r_cmb * 256 +       u_cmb]);
            const float pf = sigf  (pre_s[r_cmb * 256 +  64 + u_cmb]);
            const float pg = tanhf2(pre_s[r_cmb * 256 + 128 + u_cmb]);
            const float po = sigf  (pre_s[r_cmb * 256 + 192 + u_cmb]);
            c = pf * c + pi * pg;
            const float h = po * tanhf2(c);
            h_s[r_cmb * 64 + u_cmb] = h;
            g_h0[((long)(b0 + r_cmb) * T + t) * 128 + dir * 64 + u_cmb] = h;
        }
    }
}

// =======================================================================
// Transpose layer-1 input weights into [k][n] (n = dir*256 + gate_row).
// =======================================================================
__global__ void prep_bt(const float* __restrict__ Wf, const float* __restrict__ Wb)
{
    const int idx = blockIdx.x * 512 + threadIdx.x;   // 65536 total
    const int k = idx >> 9, n = idx & 511;
    const float* W = (n & 256) ? Wb : Wf;
    g_Bt[idx] = W[(n & 255) * 128 + k];
}

// =======================================================================
// xp1 GEMM: [262144 x 512] = h0 [262144 x 128] @ Bt^T, + bias.
// 128x128 tile, K=128 in one smem shot, 8x8 microtile, FFMA2 packed along M.
// grid = (2048, 4), block = 256.
// =======================================================================
constexpr int GP = 132;                                     // A smem pad (k-major)
constexpr int SMEM_GEMM = (128 * GP + 128 * 128) * 4;       // 133120 B

__global__ __launch_bounds__(256, 1) void gemm_xp1(
    const float* __restrict__ bias_f, const float* __restrict__ bias_b)
{
    extern __shared__ float sm[];
    float* As = sm;                 // As[k*GP + m]
    float* Bs = sm + 128 * GP;      // Bs[k*128 + n]
    const int tid = threadIdx.x;
    const long m0 = (long)blockIdx.x * 128;
    const int  n0 = blockIdx.y * 128;

    // A tile: transpose h0 rows into k-major
    #pragma unroll
    for (int i = 0; i < 16; i++) {
        const int e = tid + i * 256;
        const int m = e >> 5, k4 = e & 31;
        const float4 v = *(const float4*)(g_h0 + (m0 + m) * 128 + k4 * 4);
        As[(k4 * 4 + 0) * GP + m] = v.x;
        As[(k4 * 4 + 1) * GP + m] = v.y;
        As[(k4 * 4 + 2) * GP + m] = v.z;
        As[(k4 * 4 + 3) * GP + m] = v.w;
    }
    // B tile: already k-major, straight copy
    #pragma unroll
    for (int i = 0; i < 16; i++) {
        const int e = tid + i * 256;
        const int k = e >> 5, n4 = e & 31;
        *(float4*)(Bs + k * 128 + n4 * 4) = *(const float4*)(g_Bt + k * 512 + n0 + n4 * 4);
    }
    __syncthreads();

    const int tx = tid & 15, ty = tid >> 4;
    ULL acc[4][8];
    #pragma unroll
    for (int i = 0; i < 4; i++)
        #pragma unroll
        for (int j = 0; j < 8; j++) acc[i][j] = 0;

    #pragma unroll 4
    for (int k = 0; k < 128; k++) {
        ULL a2[4];
        const ULL* ap = (const ULL*)(As + k * GP + ty * 8);  // natural (m,m+1) pairs
        a2[0] = ap[0]; a2[1] = ap[1]; a2[2] = ap[2]; a2[3] = ap[3];
        const float* bp = Bs + k * 128 + tx * 8;
        #pragma unroll
        for (int j = 0; j < 8; j++) {
            const float bv = bp[j];
            const ULL bj = pack2(bv, bv);
            #pragma unroll
            for (int i = 0; i < 4; i++) ffma2(acc[i][j], a2[i], bj);
        }
    }

    const float* bptr = (n0 & 256) ? bias_b : bias_f;
    #pragma unroll
    for (int j = 0; j < 8; j++) {
        const int n = n0 + tx * 8 + j;
        const float bv = bptr[n & 255];
        #pragma unroll
        for (int i = 0; i < 4; i++) {
            const float2 v = unpack2(acc[i][j]);
            const long m = m0 + ty * 8 + i * 2;
            g_xp1[m * 512 + n]       = v.x + bv;
            g_xp1[(m + 1) * 512 + n] = v.y + bv;
        }
    }
}

// =======================================================================
// Layer-1 bidirectional LSTM: preacts streamed from g_xp1, W_hh in registers,
// pooled sum over t accumulated in registers (no h1 buffer).
// =======================================================================
__global__ __launch_bounds__(512, 1) void lstm_l1(
    const float* __restrict__ Whh_f, const float* __restrict__ Whh_b)
{
    const int dir = blockIdx.y;
    const int b0  = blockIdx.x * RC;
    const int tid = threadIdx.x;
    const int rr  = tid >> 8;
    const int g   = (tid >> 6) & 3;
    const int u   = tid & 63;
    const int row = g * 64 + u;
    const float* Whh = dir ? Whh_b : Whh_f;

    __shared__ float h_s[RC * 64];
    __shared__ float pre_s[RC * 256];

    ULL w2[32];
    {
        const ULL* wp = (const ULL*)(Whh + row * 64);
        #pragma unroll
        for (int i = 0; i < 32; i++) w2[i] = wp[i];
    }
    for (int i = tid; i < RC * 64; i += 512) h_s[i] = 0.f;

    float c = 0.f, hsum = 0.f;
    const int r_cmb = tid >> 6;
    const int u_cmb = tid & 63;
    const int col = dir * 256 + row;

    for (int s = 0; s < T; s++) {
        const int t = dir ? (T - 1 - s) : s;
        __syncthreads();
        #pragma unroll
        for (int j = 0; j < 4; j++) {
            const int r = rr * 4 + j;
            const float xp = __ldg(g_xp1 + ((long)(b0 + r) * T + t) * 512 + col);
            ULL a0 = 0, a1 = 0;
            const ulonglong2* h4 = (const ulonglong2*)(h_s + r * 64);
            #pragma unroll
            for (int k4 = 0; k4 < 16; k4++) {
                ulonglong2 hv = h4[k4];
                ffma2(a0, w2[2 * k4],     hv.x);
                ffma2(a1, w2[2 * k4 + 1], hv.y);
            }
            const float2 f0 = unpack2(a0), f1 = unpack2(a1);
            pre_s[r * 256 + row] = f0.x + f0.y + f1.x + f1.y + xp;
        }
        __syncthreads();
        {
            const float pi = sigf  (pre_s[r_cmb * 256 +       u_cmb]);
            const float pf = sigf  (pre_s[r_cmb * 256 +  64 + u_cmb]);
            const float pg = tanhf2(pre_s[r_cmb * 256 + 128 + u_cmb]);
            const float po = sigf  (pre_s[r_cmb * 256 + 192 + u_cmb]);
            c = pf * c + pi * pg;
            const float h = po * tanhf2(c);
            h_s[r_cmb * 64 + u_cmb] = h;
            hsum += h;
        }
    }
    g_pooled[(b0 + r_cmb) * 128 + dir * 64 + u_cmb] = hsum;
}

// =======================================================================
// Final: out[b] = mean_t(h1[b]) . fc_w + fc_b   (one warp per b)
// =======================================================================
__global__ void fc_kernel(const float* __restrict__ fcw, const float* __restrict__ fcb,
                          float* __restrict__ out)
{
    const int gw   = (blockIdx.x * blockDim.x + threadIdx.x) >> 5;
    const int lane = threadIdx.x & 31;
    if (gw >= B) return;
    float sum = 0.f;
    #pragma unroll
    for (int q = 0; q < 4; q++)
        sum += g_pooled[gw * 128 + q * 32 + lane] * fcw[q * 32 + lane];
    #pragma unroll
    for (int o = 16; o; o >>= 1) sum += __shfl_xor_sync(0xffffffffu, sum, o);
    if (lane == 0) out[gw] = sum * (1.f / 512.f) + fcb[0];
}

// =======================================================================
extern "C" void kernel_launch(void* const* d_in, const int* in_sizes, int n_in,
                              void* d_out, int out_size)
{
    const float* x     = (const float*)d_in[0];
    const float* Wih0f = (const float*)d_in[1];
    const float* Whh0f = (const float*)d_in[2];
    const float* b0f   = (const float*)d_in[3];
    const float* Wih0b = (const float*)d_in[4];
    const float* Whh0b = (const float*)d_in[5];
    const float* b0b   = (const float*)d_in[6];
    const float* Wih1f = (const float*)d_in[7];
    const float* Whh1f = (const float*)d_in[8];
    const float* b1f   = (const float*)d_in[9];
    const float* Wih1b = (const float*)d_in[10];
    const float* Whh1b = (const float*)d_in[11];
    const float* b1b   = (const float*)d_in[12];
    const float* fcw   = (const float*)d_in[13];
    const float* fcb   = (const float*)d_in[14];

    prep_bt<<<128, 512>>>(Wih1f, Wih1b);
    lstm_l0<<<dim3(NCHUNK, 2), 512>>>(x, Wih0f, Whh0f, b0f, Wih0b, Whh0b, b0b);
    cudaFuncSetAttribute(gemm_xp1, cudaFuncAttributeMaxDynamicSharedMemorySize, SMEM_GEMM);
    gemm_xp1<<<dim3(2048, 4), 256, SMEM_GEMM>>>(b1f, b1b);
    lstm_l1<<<dim3(NCHUNK, 2), 512>>>(Whh1f, Whh1b);
    fc_kernel<<<32, 512>>>(fcw, fcb, (float*)d_out);
}

// round 2
// speedup vs baseline: 1.1211x; 1.1211x over previous
#include <cuda_runtime.h>

typedef unsigned long long ULL;

// ---------- packed fp32x2 helpers ----------
__device__ __forceinline__ void ffma2(ULL &d, ULL a, ULL b) {
    asm("fma.rn.f32x2 %0, %1, %2, %0;" : "+l"(d) : "l"(a), "l"(b));
}
__device__ __forceinline__ float2 unpack2(ULL v) {
    float2 f; asm("mov.b64 {%0,%1}, %2;" : "=f"(f.x), "=f"(f.y) : "l"(v)); return f;
}
__device__ __forceinline__ ULL pack2(float lo, float hi) {
    ULL r; asm("mov.b64 %0, {%1,%2};" : "=l"(r) : "f"(lo), "f"(hi)); return r;
}
__device__ __forceinline__ ULL dup2(float a) {
    ULL r; asm("mov.b64 %0, {%1,%1};" : "=l"(r) : "f"(a)); return r;
}
__device__ __forceinline__ ULL add2(ULL a, ULL b) {
    ULL r; asm("add.rn.f32x2 %0, %1, %2;" : "=l"(r) : "l"(a), "l"(b)); return r;
}

// ---------- activations (MUFU ex2+rcp based; proven 1.8e-7 accuracy) ----------
__device__ __forceinline__ float sigf(float x)  { return __fdividef(1.f, 1.f + __expf(-x)); }
__device__ __forceinline__ float tanhf2(float x){ return 2.f * sigf(2.f * x) - 1.f; }

// ---------- problem constants ----------
constexpr int B = 512, T = 512;
constexpr int RC = 4;              // batch rows per LSTM CTA

// ---------- scratch ----------
__device__ float g_h0[(long)B * T * 128];     // layer-0 output  [b][t][dir*64+u]
__device__ float g_xp1[(long)B * T * 512];    // layer-1 preacts [b*T+t][dir*256+row]
__device__ float g_Bt[128 * 512];             // Wih_l1 transposed [k][n]
__device__ float g_pooled[B * 128];           // sum over t of h1

// =======================================================================
// Layer-0 biLSTM. grid (128, 2), block 256, 2 CTAs/SM.
// Thread: u = tid>>2, g = tid&3 -> owns gate row g*64+u (weights in regs),
// computes that gate for 4 batch rows (j). Gate exchange via lane-quad shfl.
// One __syncthreads per step (h double-buffered in smem). x staged via smem.
// =======================================================================
__global__ __launch_bounds__(256, 2) void lstm_l0(
    const float* __restrict__ x,
    const float* __restrict__ Wih_f, const float* __restrict__ Whh_f, const float* __restrict__ b_f,
    const float* __restrict__ Wih_b, const float* __restrict__ Whh_b, const float* __restrict__ b_b)
{
    const int dir = blockIdx.y;
    const int b0  = blockIdx.x * RC;
    const int tid = threadIdx.x;
    const int u   = tid >> 2;
    const int g   = tid & 3;
    const int row = g * 64 + u;

    const float* Wih = dir ? Wih_b : Wih_f;
    const float* Whh = dir ? Whh_b : Whh_f;
    const float* bb  = dir ? b_b   : b_f;

    __shared__ __align__(16) float h_s[2][RC * 64];
    __shared__ __align__(16) float4 x_s[2][RC];

    ULL w2[32];
    {
        const ULL* wp = (const ULL*)(Whh + row * 64);
        #pragma unroll
        for (int i = 0; i < 32; i++) w2[i] = wp[i];
    }
    const float4 wih = *(const float4*)(Wih + row * 4);
    const float bias = bb[row];

    const int lane  = tid & 31;
    const int qb    = lane & ~3;

    for (int i = tid; i < RC * 64; i += 256) h_s[0][i] = 0.f;
    if (tid < RC) {
        const int t0 = dir ? (T - 1) : 0;
        x_s[0][tid] = *(const float4*)(x + ((long)(b0 + tid) * T + t0) * 4);
    }
    __syncthreads();

    float c[RC] = {0.f, 0.f, 0.f, 0.f};
    int p = 0;

    for (int s = 0; s < T; s++) {
        const int t  = dir ? (T - 1 - s) : s;
        // stage next step's x (warp-uniform data -> smem via 4 threads)
        if (tid < RC) {
            const int sn = (s + 1 < T) ? s + 1 : s;
            const int tn = dir ? (T - 1 - sn) : sn;
            x_s[p ^ 1][tid] = *(const float4*)(x + ((long)(b0 + tid) * T + tn) * 4);
        }

        float pre[RC];
        #pragma unroll
        for (int j = 0; j < RC; j++) {
            ULL a0 = 0, a1 = 0;
            const ulonglong2* h4 = (const ulonglong2*)(h_s[p] + j * 64);
            #pragma unroll
            for (int k = 0; k < 16; k++) {
                ulonglong2 hv = h4[k];
                ffma2(a0, w2[2 * k],     hv.x);
                ffma2(a1, w2[2 * k + 1], hv.y);
            }
            const float2 f0 = unpack2(a0), f1 = unpack2(a1);
            const float4 xv = x_s[p][j];
            pre[j] = f0.x + f0.y + f1.x + f1.y + bias
                   + wih.x * xv.x + wih.y * xv.y + wih.z * xv.z + wih.w * xv.w;
        }

        #pragma unroll
        for (int j = 0; j < RC; j++) {
            // own-gate activation: g==2 -> tanh, else sigmoid
            const float act = (g == 2) ? tanhf2(pre[j]) : sigf(pre[j]);
            const float iv = __shfl_sync(0xffffffffu, act, qb + 0);
            const float fv = __shfl_sync(0xffffffffu, act, qb + 1);
            const float gv = __shfl_sync(0xffffffffu, act, qb + 2);
            const float ov = __shfl_sync(0xffffffffu, act, qb + 3);
            c[j] = fmaf(fv, c[j], iv * gv);
            const float h = ov * tanhf2(c[j]);
            if (g == 0) {
                h_s[p ^ 1][j * 64 + u] = h;
                g_h0[((long)(b0 + j) * T + t) * 128 + dir * 64 + u] = h;
            }
        }
        p ^= 1;
        __syncthreads();
    }
}

// =======================================================================
// Transpose layer-1 input weights into [k][n] (n = dir*256 + row).
// =======================================================================
__global__ void prep_bt(const float* __restrict__ Wf, const float* __restrict__ Wb)
{
    const int idx = blockIdx.x * 512 + threadIdx.x;   // 65536 total
    const int k = idx >> 9, n = idx & 511;
    const float* W = (n & 256) ? Wb : Wf;
    g_Bt[idx] = W[(n & 255) * 128 + k];
}

// =======================================================================
// xp1 GEMM: [262144 x 512] = h0 [262144 x 128] @ Bt, + bias.
// 128x128 tile, K=128 one shot. A stored PRE-DUPLICATED as (a,a) f32x2 in
// smem (no transpose, no conflicts); B read as natural (n,n+1) pairs with
// lane-consecutive n (conflict-free). FFMA2 packs along N. Coalesced STG.64.
// grid (2048, 4), block 256.
// =======================================================================
constexpr int SMEM_GEMM = 128 * 128 * 8 + 128 * 128 * 4;   // 196608 B

__global__ __launch_bounds__(256, 1) void gemm_xp1(
    const float* __restrict__ bias_f, const float* __restrict__ bias_b)
{
    extern __shared__ char smraw[];
    ULL*   As2 = (ULL*)smraw;                         // [m*128 + k], (a,a) pairs
    float* Bs  = (float*)(smraw + 128 * 128 * 8);     // [k*128 + n]
    const int tid = threadIdx.x;
    const long m0 = (long)blockIdx.x * 128;
    const int  n0 = blockIdx.y * 128;

    // A tile: straight m-major float4 loads, store duplicated pairs
    #pragma unroll
    for (int i = 0; i < 16; i++) {
        const int e = tid + i * 256;
        const int m = e >> 5, kq = (e & 31) * 4;
        const float4 v = *(const float4*)(g_h0 + (m0 + m) * 128 + kq);
        ULL* dst = As2 + m * 128 + kq;
        *(ulonglong2*)(dst)     = make_ulonglong2(dup2(v.x), dup2(v.y));
        *(ulonglong2*)(dst + 2) = make_ulonglong2(dup2(v.z), dup2(v.w));
    }
    // B tile: already k-major, straight copy
    #pragma unroll
    for (int i = 0; i < 16; i++) {
        const int e = tid + i * 256;
        const int k = e >> 5, n4 = (e & 31) * 4;
        *(float4*)(Bs + k * 128 + n4) = *(const float4*)(g_Bt + k * 512 + n0 + n4);
    }
    __syncthreads();

    const int tx = tid & 15;        // n:  pairs at jj*32 + tx*2
    const int ty = tid >> 4;        // m:  block ty*8
    ULL acc[8][4];
    #pragma unroll
    for (int i = 0; i < 8; i++)
        #pragma unroll
        for (int jj = 0; jj < 4; jj++) acc[i][jj] = 0;

    #pragma unroll 8
    for (int k = 0; k < 128; k++) {
        ULL a[8];
        #pragma unroll
        for (int i = 0; i < 8; i++) a[i] = As2[(ty * 8 + i) * 128 + k];
        ULL b[4];
        #pragma unroll
        for (int jj = 0; jj < 4; jj++) b[jj] = *(const ULL*)(Bs + k * 128 + jj * 32 + tx * 2);
        #pragma unroll
        for (int i = 0; i < 8; i++)
            #pragma unroll
            for (int jj = 0; jj < 4; jj++) ffma2(acc[i][jj], a[i], b[jj]);
    }

    const float* bptr = (n0 & 256) ? bias_b : bias_f;
    ULL bias2[4];
    #pragma unroll
    for (int jj = 0; jj < 4; jj++) {
        const int n = n0 + jj * 32 + tx * 2;
        bias2[jj] = pack2(bptr[n & 255], bptr[(n + 1) & 255]);
    }
    #pragma unroll
    for (int i = 0; i < 8; i++) {
        const long m = m0 + ty * 8 + i;
        float* orow = g_xp1 + m * 512;
        #pragma unroll
        for (int jj = 0; jj < 4; jj++) {
            const int n = n0 + jj * 32 + tx * 2;
            *(ULL*)(orow + n) = add2(acc[i][jj], bias2[jj]);
        }
    }
}

// =======================================================================
// Layer-1 biLSTM: same structure as l0; preacts prefetched one step ahead
// from g_xp1 into registers; pooled sum accumulated in registers.
// =======================================================================
__global__ __launch_bounds__(256, 2) void lstm_l1(
    const float* __restrict__ Whh_f, const float* __restrict__ Whh_b)
{
    const int dir = blockIdx.y;
    const int b0  = blockIdx.x * RC;
    const int tid = threadIdx.x;
    const int u   = tid >> 2;
    const int g   = tid & 3;
    const int row = g * 64 + u;
    const float* Whh = dir ? Whh_b : Whh_f;

    __shared__ __align__(16) float h_s[2][RC * 64];

    ULL w2[32];
    {
        const ULL* wp = (const ULL*)(Whh + row * 64);
        #pragma unroll
        for (int i = 0; i < 32; i++) w2[i] = wp[i];
    }
    const int lane = tid & 31;
    const int qb   = lane & ~3;
    const int col  = dir * 256 + row;

    const float* xp_base[RC];
    #pragma unroll
    for (int j = 0; j < RC; j++)
        xp_base[j] = g_xp1 + (long)(b0 + j) * T * 512 + col;

    for (int i = tid; i < RC * 64; i += 256) h_s[0][i] = 0.f;

    float c[RC]    = {0.f, 0.f, 0.f, 0.f};
    float hsum[RC] = {0.f, 0.f, 0.f, 0.f};
    float xp_cur[RC];
    {
        const int t0 = dir ? (T - 1) : 0;
        #pragma unroll
        for (int j = 0; j < RC; j++) xp_cur[j] = __ldg(xp_base[j] + (long)t0 * 512);
    }
    __syncthreads();

    int p = 0;
    for (int s = 0; s < T; s++) {
        // prefetch next step's preacts
        const int sn = (s + 1 < T) ? s + 1 : s;
        const int tn = dir ? (T - 1 - sn) : sn;
        float xp_nxt[RC];
        #pragma unroll
        for (int j = 0; j < RC; j++) xp_nxt[j] = __ldg(xp_base[j] + (long)tn * 512);

        float pre[RC];
        #pragma unroll
        for (int j = 0; j < RC; j++) {
            ULL a0 = 0, a1 = 0;
            const ulonglong2* h4 = (const ulonglong2*)(h_s[p] + j * 64);
            #pragma unroll
            for (int k = 0; k < 16; k++) {
                ulonglong2 hv = h4[k];
                ffma2(a0, w2[2 * k],     hv.x);
                ffma2(a1, w2[2 * k + 1], hv.y);
            }
            const float2 f0 = unpack2(a0), f1 = unpack2(a1);
            pre[j] = f0.x + f0.y + f1.x + f1.y + xp_cur[j];
        }

        #pragma unroll
        for (int j = 0; j < RC; j++) {
            const float act = (g == 2) ? tanhf2(pre[j]) : sigf(pre[j]);
            const float iv = __shfl_sync(0xffffffffu, act, qb + 0);
            const float fv = __shfl_sync(0xffffffffu, act, qb + 1);
            const float gv = __shfl_sync(0xffffffffu, act, qb + 2);
            const float ov = __shfl_sync(0xffffffffu, act, qb + 3);
            c[j] = fmaf(fv, c[j], iv * gv);
            const float h = ov * tanhf2(c[j]);
            hsum[j] += h;
            if (g == 0) h_s[p ^ 1][j * 64 + u] = h;
        }
        #pragma unroll
        for (int j = 0; j < RC; j++) xp_cur[j] = xp_nxt[j];
        p ^= 1;
        __syncthreads();
    }

    if (g == 0) {
        #pragma unroll
        for (int j = 0; j < RC; j++)
            g_pooled[(b0 + j) * 128 + dir * 64 + u] = hsum[j];
    }
}

// =======================================================================
// Final: out[b] = mean_t(h1[b]) . fc_w + fc_b   (one warp per b)
// =======================================================================
__global__ void fc_kernel(const float* __restrict__ fcw, const float* __restrict__ fcb,
                          float* __restrict__ out)
{
    const int gw   = (blockIdx.x * blockDim.x + threadIdx.x) >> 5;
    const int lane = threadIdx.x & 31;
    if (gw >= B) return;
    float sum = 0.f;
    #pragma unroll
    for (int q = 0; q < 4; q++)
        sum += g_pooled[gw * 128 + q * 32 + lane] * fcw[q * 32 + lane];
    #pragma unroll
    for (int o = 16; o; o >>= 1) sum += __shfl_xor_sync(0xffffffffu, sum, o);
    if (lane == 0) out[gw] = sum * (1.f / 512.f) + fcb[0];
}

// =======================================================================
extern "C" void kernel_launch(void* const* d_in, const int* in_sizes, int n_in,
                              void* d_out, int out_size)
{
    const float* x     = (const float*)d_in[0];
    const float* Wih0f = (const float*)d_in[1];
    const float* Whh0f = (const float*)d_in[2];
    const float* b0f   = (const float*)d_in[3];
    const float* Wih0b = (const float*)d_in[4];
    const float* Whh0b = (const float*)d_in[5];
    const float* b0b   = (const float*)d_in[6];
    const float* Wih1f = (const float*)d_in[7];
    const float* Whh1f = (const float*)d_in[8];
    const float* b1f   = (const float*)d_in[9];
    const float* Wih1b = (const float*)d_in[10];
    const float* Whh1b = (const float*)d_in[11];
    const float* b1b   = (const float*)d_in[12];
    const float* fcw   = (const float*)d_in[13];
    const float* fcb   = (const float*)d_in[14];

    prep_bt<<<128, 512>>>(Wih1f, Wih1b);
    lstm_l0<<<dim3(B / RC, 2), 256>>>(x, Wih0f, Whh0f, b0f, Wih0b, Whh0b, b0b);
    cudaFuncSetAttribute(gemm_xp1, cudaFuncAttributeMaxDynamicSharedMemorySize, SMEM_GEMM);
    gemm_xp1<<<dim3(2048, 4), 256, SMEM_GEMM>>>(b1f, b1b);
    lstm_l1<<<dim3(B / RC, 2), 256>>>(Whh1f, Whh1b);
    fc_kernel<<<32, 512>>>(fcw, fcb, (float*)d_out);
}